// round 9
// baseline (speedup 1.0000x reference)
#include <cuda_runtime.h>
#include <cuda_fp16.h>
#include <cstdint>
#include <math.h>

// ---------------- problem constants ----------------
#define T_TOK 8192
#define NEXP  8
#define DDIM  1024
#define HDIM  4096
#define NPAIR (2 * T_TOK)

// ---------------- device scratch (static; keep total well under 256 MB) ----------------
__device__ __half g_xh [(size_t)T_TOK * DDIM];          // x in fp16             16 MB
__device__ __half g_h  [(size_t)NPAIR * HDIM];          // compact hidden rows  128 MB
__device__ int    g_cnt [NEXP];
__device__ int    g_base[NEXP];
__device__ int    g_elist[NEXP * T_TOK];
__device__ float  g_ew  [NEXP * T_TOK];

// ---------------- helpers ----------------
__device__ __forceinline__ uint32_t smem_to_u32(const void* p) {
    uint32_t a;
    asm("{ .reg .u64 t; cvta.to.shared.u64 t, %1; cvt.u32.u64 %0, t; }" : "=r"(a) : "l"(p));
    return a;
}

#define CP_ASYNC16(dst, src) \
    asm volatile("cp.async.cg.shared.global [%0], [%1], 16;" :: "r"(dst), "l"(src) : "memory")

#define MMA16816(c, a, b0v, b1v) \
    asm volatile("mma.sync.aligned.m16n8k16.row.col.f32.f16.f16.f32 " \
        "{%0,%1,%2,%3}, {%4,%5,%6,%7}, {%8,%9}, {%0,%1,%2,%3};" \
        : "+f"((c)[0]), "+f"((c)[1]), "+f"((c)[2]), "+f"((c)[3]) \
        : "r"((a)[0]), "r"((a)[1]), "r"((a)[2]), "r"((a)[3]), "r"(b0v), "r"(b1v))

__device__ __forceinline__ float gelu_f(float v) {
    return 0.5f * v * (1.0f + erff(v * 0.70710678118654752440f));
}

// ---------------- SMEM layout (dynamic, 86016 B) ----------------
// stage: 2 x 32k x 132f fp32 (16896 B each)
// Ash:   2 x 256 rows x 40 halves (20480 B each)
// Bsh:   128 rows x 40 halves (10240 B)
// stok:  256 ints
#define OFF_STAGE0 0
#define OFF_STAGE1 16896
#define OFF_ASH0   33792
#define OFF_ASH1   54272
#define OFF_BSH    74752
#define OFF_TOK    84992
#define SMEM_BYTES 86016

// ---------------- small kernels ----------------
__global__ void zero_out_kernel(float4* __restrict__ out) {
    size_t i = (size_t)blockIdx.x * 512 + threadIdx.x;
    out[i] = make_float4(0.f, 0.f, 0.f, 0.f);
    if (blockIdx.x == 0 && threadIdx.x < NEXP) g_cnt[threadIdx.x] = 0;
}

__global__ void convert_x_kernel(const float* __restrict__ x) {
    size_t i = (size_t)blockIdx.x * 256 + threadIdx.x;     // over float4s
    float4 v = ((const float4*)x)[i];
    ((__half2*)g_xh)[2 * i]     = __floats2half2_rn(v.x, v.y);
    ((__half2*)g_xh)[2 * i + 1] = __floats2half2_rn(v.z, v.w);
}

__global__ void prefix_kernel() {
    if (threadIdx.x == 0) {
        int s = 0;
#pragma unroll
        for (int e = 0; e < NEXP; e++) { g_base[e] = s; s += g_cnt[e]; }
    }
}

// ---------------- routing ----------------
__global__ __launch_bounds__(256) void route_kernel(const float* __restrict__ x,
                                                    const float* __restrict__ wg) {
    int t = blockIdx.x * 8 + (threadIdx.x >> 5);
    int lane = threadIdx.x & 31;
    const float* xr = x + (size_t)t * DDIM;
    float acc[NEXP];
#pragma unroll
    for (int e = 0; e < NEXP; e++) acc[e] = 0.f;
    for (int d = lane; d < DDIM; d += 32) {
        float xv = xr[d];
        const float* wr = wg + d * NEXP;
#pragma unroll
        for (int e = 0; e < NEXP; e++) acc[e] += xv * wr[e];
    }
#pragma unroll
    for (int e = 0; e < NEXP; e++)
#pragma unroll
        for (int off = 16; off; off >>= 1)
            acc[e] += __shfl_xor_sync(0xffffffffu, acc[e], off);
    if (lane == 0) {
        float m = acc[0];
#pragma unroll
        for (int e = 1; e < NEXP; e++) m = fmaxf(m, acc[e]);
        float p[NEXP], s = 0.f;
#pragma unroll
        for (int e = 0; e < NEXP; e++) { p[e] = expf(acc[e] - m); s += p[e]; }
        float inv = 1.f / s;
#pragma unroll
        for (int e = 0; e < NEXP; e++) p[e] *= inv;
        int i0 = 0;
#pragma unroll
        for (int e = 1; e < NEXP; e++) if (p[e] > p[i0]) i0 = e;
        int i1 = (i0 == 0) ? 1 : 0;
#pragma unroll
        for (int e = 0; e < NEXP; e++) if (e != i0 && p[e] > p[i1]) i1 = e;
        int pos = atomicAdd(&g_cnt[i0], 1);
        g_elist[i0 * T_TOK + pos] = t; g_ew[i0 * T_TOK + pos] = p[i0];
        pos = atomicAdd(&g_cnt[i1], 1);
        g_elist[i1 * T_TOK + pos] = t; g_ew[i1 * T_TOK + pos] = p[i1];
    }
}

// ---------------- grouped GEMM: BM=256, BN=128, BK=32, 512 threads ----------------
// 16 warps = 4(M) x 4(N); warp tile 64x32 -> 4x4 m16n8k16, acc[4][4][4].
// cp.async double-buffered; prefetch issued after second barrier (race-free, R8-validated).
// G1:  C = gather(x fp16)[256,1024] @ W1[e] -> +b1 -> gelu -> g_h[base+slot]
// !G1: C = g_h[base+r][256,4096] @ W2[e] -> (+b2)*w -> atomicAdd out
template <int KDIM, bool G1>
__global__ __launch_bounds__(512) void moe_mma_kernel(const float* __restrict__ Wsrc,
                                                      const float* __restrict__ bias,
                                                      float* __restrict__ out) {
    extern __shared__ __align__(16) char smem[];
    float*  stage[2] = {(float*)(smem + OFF_STAGE0), (float*)(smem + OFF_STAGE1)};
    __half* Ash[2]   = {(__half*)(smem + OFF_ASH0), (__half*)(smem + OFF_ASH1)};
    __half* Bsh      = (__half*)(smem + OFF_BSH);
    int*    stok     = (int*)(smem + OFF_TOK);
    const uint32_t sb = smem_to_u32(smem);

    const int e = blockIdx.z;
    const int cnt = g_cnt[e];
    const int m0 = blockIdx.y * 256;
    if (m0 >= cnt) return;
    const int base = g_base[e];
    const int n0 = blockIdx.x * 128;
    const int tid = threadIdx.x;
    const int lane = tid & 31, wid = tid >> 5;
    const int wm = wid & 3, wn = wid >> 2;          // 4 x 4 warp grid
    constexpr int NDIM = G1 ? HDIM : DDIM;

    if (tid < 256) {
        int r = m0 + tid; if (r >= cnt) r = cnt - 1;
        stok[tid] = G1 ? g_elist[e * T_TOK + r] : (base + r);
    }
    __syncthreads();

    const __half* Abase = G1 ? g_xh : g_h;
    const float* Bsrc = Wsrc + (size_t)e * DDIM * HDIM;

    auto issue_loads = [&](int it, int b) {
        const int k0 = it * 32;
        const uint32_t abuf = sb + (b ? OFF_ASH1 : OFF_ASH0);
        const uint32_t sbuf = sb + (b ? OFF_STAGE1 : OFF_STAGE0);
        // A: 256 rows x 32 k fp16 = 1024 x 16B chunks (2 per thread)
#pragma unroll
        for (int j = 0; j < 2; j++) {
            int u = tid + j * 512;
            int m = u >> 2, kq = u & 3;
            CP_ASYNC16(abuf + m * 80 + kq * 16,
                       Abase + (size_t)stok[m] * KDIM + k0 + kq * 8);
        }
        // B: 32 k x 128 n fp32 = 1024 x 16B chunks (2 per thread)
#pragma unroll
        for (int j = 0; j < 2; j++) {
            int u = tid + j * 512;
            int k = u >> 5, nq = u & 31;
            CP_ASYNC16(sbuf + (k * 132 + nq * 4) * 4,
                       Bsrc + (size_t)(k0 + k) * NDIM + n0 + nq * 4);
        }
        asm volatile("cp.async.commit_group;" ::: "memory");
    };

    float acc[4][4][4];
#pragma unroll
    for (int i = 0; i < 4; i++)
#pragma unroll
        for (int j = 0; j < 4; j++)
#pragma unroll
            for (int k = 0; k < 4; k++) acc[i][j][k] = 0.f;

    const int qr = lane >> 2;
    const int qc = (lane & 3) * 2;
    const int tn = tid & 127, tkh = tid >> 7;       // tkh 0..3, 8 k each

    constexpr int NIT = KDIM / 32;
    issue_loads(0, 0);

#pragma unroll 1
    for (int i = 0; i < NIT; i++) {
        asm volatile("cp.async.wait_group 0;" ::: "memory");   // group i landed
        __syncthreads();

        // transpose + convert: stage[i&1] [k][n] -> Bsh [n][k] (8 k per thread)
        {
            const float* st = stage[i & 1];
            __half2 hbuf[4];
#pragma unroll
            for (int kk = 0; kk < 8; kk += 2)
                hbuf[kk / 2] = __floats2half2_rn(st[(tkh * 8 + kk) * 132 + tn],
                                                 st[(tkh * 8 + kk + 1) * 132 + tn]);
            *(uint4*)(Bsh + tn * 40 + tkh * 8) = *(const uint4*)(hbuf);
        }
        __syncthreads();   // Bsh ready; all prior readers of buffers (i+1)&1 are done

        if (i + 1 < NIT) issue_loads(i + 1, (i + 1) & 1);   // overlaps MMA below

        const __half* As = Ash[i & 1];
#pragma unroll
        for (int ks = 0; ks < 2; ks++) {
            const int kk = ks * 16 + qc;
            uint32_t a[4][4];
#pragma unroll
            for (int mt = 0; mt < 4; mt++) {
                const __half* p = As + (wm * 64 + mt * 16 + qr) * 40 + kk;
                a[mt][0] = *(const uint32_t*)(p);
                a[mt][1] = *(const uint32_t*)(p + 320);
                a[mt][2] = *(const uint32_t*)(p + 8);
                a[mt][3] = *(const uint32_t*)(p + 328);
            }
            uint32_t bfr[4][2];
#pragma unroll
            for (int nt = 0; nt < 4; nt++) {
                const __half* p = Bsh + (wn * 32 + nt * 8 + qr) * 40 + kk;
                bfr[nt][0] = *(const uint32_t*)(p);
                bfr[nt][1] = *(const uint32_t*)(p + 8);
            }
#pragma unroll
            for (int mt = 0; mt < 4; mt++)
#pragma unroll
                for (int nt = 0; nt < 4; nt++)
                    MMA16816(acc[mt][nt], a[mt], bfr[nt][0], bfr[nt][1]);
        }
    }

    const int r0 = lane >> 2;
    const int c0l = (lane & 3) * 2;

    if (G1) {
#pragma unroll
        for (int mt = 0; mt < 4; mt++)
#pragma unroll
            for (int hr = 0; hr < 2; hr++) {
                int slot = m0 + wm * 64 + mt * 16 + hr * 8 + r0;
                if (slot < cnt) {
                    __half* hrow = g_h + (size_t)(base + slot) * HDIM;
#pragma unroll
                    for (int nt = 0; nt < 4; nt++) {
                        int n = n0 + wn * 32 + nt * 8 + c0l;
                        float v0 = acc[mt][nt][hr * 2]     + bias[(size_t)e * NDIM + n];
                        float v1 = acc[mt][nt][hr * 2 + 1] + bias[(size_t)e * NDIM + n + 1];
                        *(__half2*)(hrow + n) = __floats2half2_rn(gelu_f(v0), gelu_f(v1));
                    }
                }
            }
    } else {
#pragma unroll
        for (int mt = 0; mt < 4; mt++)
#pragma unroll
            for (int hr = 0; hr < 2; hr++) {
                int slot = m0 + wm * 64 + mt * 16 + hr * 8 + r0;
                if (slot < cnt) {
                    int tok = g_elist[e * T_TOK + slot];
                    float wgt = g_ew[e * T_TOK + slot];
                    float* orow = out + (size_t)tok * DDIM;
#pragma unroll
                    for (int nt = 0; nt < 4; nt++) {
                        int n = n0 + wn * 32 + nt * 8 + c0l;
                        float v0 = (acc[mt][nt][hr * 2]     + bias[(size_t)e * NDIM + n])     * wgt;
                        float v1 = (acc[mt][nt][hr * 2 + 1] + bias[(size_t)e * NDIM + n + 1]) * wgt;
                        atomicAdd(orow + n, v0);
                        atomicAdd(orow + n + 1, v1);
                    }
                }
            }
    }
}

// ---------------- fallback: recompute any all-zero token (insurance) ----------------
__global__ __launch_bounds__(256) void fallback_kernel(
        const float* __restrict__ x,  const float* __restrict__ Wg,
        const float* __restrict__ W1, const float* __restrict__ b1,
        const float* __restrict__ W2, const float* __restrict__ b2,
        float* __restrict__ out) {
    const int t = blockIdx.x;
    float* orow = out + (size_t)t * DDIM;
    const int tid = threadIdx.x;

    __shared__ int nz;
    if (tid == 0) nz = 0;
    __syncthreads();
    for (int d = tid; d < DDIM; d += 256)
        if (fabsf(orow[d]) > 1e-10f) nz = 1;
    __syncthreads();
    if (nz) return;

    __shared__ float sx[DDIM];
    __shared__ float sh[HDIM];
    __shared__ float slog[NEXP];
    __shared__ int   sel[2];
    __shared__ float selw[2];

    for (int d = tid; d < DDIM; d += 256) sx[d] = x[(size_t)t * DDIM + d];
    __syncthreads();

    const int wid = tid >> 5, lane = tid & 31;
    if (wid < NEXP) {
        float a = 0.f;
        for (int d = lane; d < DDIM; d += 32) a += sx[d] * Wg[d * NEXP + wid];
#pragma unroll
        for (int o = 16; o; o >>= 1) a += __shfl_xor_sync(0xffffffffu, a, o);
        if (lane == 0) slog[wid] = a;
    }
    __syncthreads();
    if (tid == 0) {
        float m = slog[0];
        for (int e = 1; e < NEXP; e++) m = fmaxf(m, slog[e]);
        float p[NEXP], s = 0.f;
        for (int e = 0; e < NEXP; e++) { p[e] = expf(slog[e] - m); s += p[e]; }
        for (int e = 0; e < NEXP; e++) p[e] /= s;
        int i0 = 0;
        for (int e = 1; e < NEXP; e++) if (p[e] > p[i0]) i0 = e;
        int i1 = (i0 == 0) ? 1 : 0;
        for (int e = 0; e < NEXP; e++) if (e != i0 && p[e] > p[i1]) i1 = e;
        sel[0] = i0; sel[1] = i1; selw[0] = p[i0]; selw[1] = p[i1];
    }
    __syncthreads();

    float yacc[4] = {0.f, 0.f, 0.f, 0.f};
#pragma unroll 1
    for (int kk = 0; kk < 2; kk++) {
        const int e = sel[kk];
        const float w = selw[kk];
        const float* w1 = W1 + (size_t)e * DDIM * HDIM;
        for (int j = tid; j < HDIM; j += 256) {
            float a = b1[e * HDIM + j];
            for (int d = 0; d < DDIM; d++) a += sx[d] * w1[(size_t)d * HDIM + j];
            sh[j] = gelu_f(a);
        }
        __syncthreads();
        const float* w2 = W2 + (size_t)e * HDIM * DDIM;
#pragma unroll
        for (int jj = 0; jj < 4; jj++) {
            int d = tid + jj * 256;
            float a = b2[e * DDIM + d];
            for (int j = 0; j < HDIM; j++) a += sh[j] * w2[(size_t)j * DDIM + d];
            yacc[jj] += w * a;
        }
        __syncthreads();
    }
#pragma unroll
    for (int jj = 0; jj < 4; jj++) orow[tid + jj * 256] = yacc[jj];
}

// ---------------- host launcher ----------------
extern "C" void kernel_launch(void* const* d_in, const int* in_sizes, int n_in,
                              void* d_out, int out_size) {
    const float* x  = (const float*)d_in[0];
    const float* Wg = (const float*)d_in[1];
    const float* W1 = (const float*)d_in[2];
    const float* b1 = (const float*)d_in[3];
    const float* W2 = (const float*)d_in[4];
    const float* b2 = (const float*)d_in[5];
    float* out = (float*)d_out;

    cudaFuncSetAttribute((const void*)moe_mma_kernel<DDIM, true>,
                         cudaFuncAttributeMaxDynamicSharedMemorySize, SMEM_BYTES);
    cudaFuncSetAttribute((const void*)moe_mma_kernel<HDIM, false>,
                         cudaFuncAttributeMaxDynamicSharedMemorySize, SMEM_BYTES);

    zero_out_kernel<<<(T_TOK * DDIM / 4) / 512, 512>>>((float4*)out);
    convert_x_kernel<<<(T_TOK * DDIM / 4) / 256, 256>>>(x);
    route_kernel<<<T_TOK / 8, 256>>>(x, Wg);
    prefix_kernel<<<1, 32>>>();
    moe_mma_kernel<DDIM, true><<<dim3(HDIM / 128, T_TOK / 256, NEXP), 512, SMEM_BYTES>>>(W1, b1, nullptr);
    moe_mma_kernel<HDIM, false><<<dim3(DDIM / 128, T_TOK / 256, NEXP), 512, SMEM_BYTES>>>(W2, b2, out);
    fallback_kernel<<<T_TOK, 256>>>(x, Wg, W1, b1, W2, b2, out);
}

// round 12
// speedup vs baseline: 1.7956x; 1.7956x over previous
#include <cuda_runtime.h>
#include <cuda_fp16.h>
#include <cstdint>
#include <math.h>

// ---------------- problem constants ----------------
#define T_TOK 8192
#define NEXP  8
#define DDIM  1024
#define HDIM  4096
#define NPAIR (2 * T_TOK)

// ---------------- device scratch (static; 208 MB total) ----------------
__device__ __half g_xh [(size_t)T_TOK * DDIM];          // x in fp16             16 MB
__device__ __half g_h  [(size_t)NPAIR * HDIM];          // compact hidden rows  128 MB
__device__ __half g_w2h[(size_t)NEXP * HDIM * DDIM];    // W2 fp16 [e][h][d]     64 MB
__device__ int    g_cnt [NEXP];
__device__ int    g_base[NEXP];
__device__ int    g_elist[NEXP * T_TOK];
__device__ float  g_ew  [NEXP * T_TOK];

// ---------------- helpers ----------------
__device__ __forceinline__ uint32_t smem_to_u32(const void* p) {
    uint32_t a;
    asm("{ .reg .u64 t; cvta.to.shared.u64 t, %1; cvt.u32.u64 %0, t; }" : "=r"(a) : "l"(p));
    return a;
}

#define CP_ASYNC16(dst, src) \
    asm volatile("cp.async.cg.shared.global [%0], [%1], 16;" :: "r"(dst), "l"(src) : "memory")

#define MMA16816(c, a, b0v, b1v) \
    asm volatile("mma.sync.aligned.m16n8k16.row.col.f32.f16.f16.f32 " \
        "{%0,%1,%2,%3}, {%4,%5,%6,%7}, {%8,%9}, {%0,%1,%2,%3};" \
        : "+f"((c)[0]), "+f"((c)[1]), "+f"((c)[2]), "+f"((c)[3]) \
        : "r"((a)[0]), "r"((a)[1]), "r"((a)[2]), "r"((a)[3]), "r"(b0v), "r"(b1v))

__device__ __forceinline__ float gelu_f(float v) {
    return 0.5f * v * (1.0f + erff(v * 0.70710678118654752440f));
}

// ---------------- SMEM layout (dynamic, 65024 B; fp32-stage worst case) ----------------
#define OFF_STAGE0 0
#define OFF_STAGE1 16896
#define OFF_ASH0   33792
#define OFF_ASH1   44032
#define OFF_BSH    54272
#define OFF_TOK    64512
#define SMEM_BYTES 65024

// ---------------- small kernels ----------------
__global__ void zero_out_kernel(float4* __restrict__ out) {
    size_t i = (size_t)blockIdx.x * 512 + threadIdx.x;
    out[i] = make_float4(0.f, 0.f, 0.f, 0.f);
    if (blockIdx.x == 0 && threadIdx.x < NEXP) g_cnt[threadIdx.x] = 0;
}

__global__ void convert_x_kernel(const float* __restrict__ x) {
    size_t i = (size_t)blockIdx.x * 256 + threadIdx.x;     // over float4s
    float4 v = ((const float4*)x)[i];
    ((__half2*)g_xh)[2 * i]     = __floats2half2_rn(v.x, v.y);
    ((__half2*)g_xh)[2 * i + 1] = __floats2half2_rn(v.z, v.w);
}

// W2 fp32 -> fp16, layout preserved (streaming)
__global__ void convert_w2_kernel(const float* __restrict__ w2) {
    size_t i = (size_t)blockIdx.x * 256 + threadIdx.x;     // over 8-float groups
    const float4* s = (const float4*)w2 + 2 * i;
    float4 a = s[0], b = s[1];
    __half2 h[4];
    h[0] = __floats2half2_rn(a.x, a.y);
    h[1] = __floats2half2_rn(a.z, a.w);
    h[2] = __floats2half2_rn(b.x, b.y);
    h[3] = __floats2half2_rn(b.z, b.w);
    ((uint4*)g_w2h)[i] = *(const uint4*)h;
}

__global__ void prefix_kernel() {
    if (threadIdx.x == 0) {
        int s = 0;
#pragma unroll
        for (int e = 0; e < NEXP; e++) { g_base[e] = s; s += g_cnt[e]; }
    }
}

// ---------------- routing ----------------
__global__ __launch_bounds__(256) void route_kernel(const float* __restrict__ x,
                                                    const float* __restrict__ wg) {
    int t = blockIdx.x * 8 + (threadIdx.x >> 5);
    int lane = threadIdx.x & 31;
    const float* xr = x + (size_t)t * DDIM;
    float acc[NEXP];
#pragma unroll
    for (int e = 0; e < NEXP; e++) acc[e] = 0.f;
    for (int d = lane; d < DDIM; d += 32) {
        float xv = xr[d];
        const float* wr = wg + d * NEXP;
#pragma unroll
        for (int e = 0; e < NEXP; e++) acc[e] += xv * wr[e];
    }
#pragma unroll
    for (int e = 0; e < NEXP; e++)
#pragma unroll
        for (int off = 16; off; off >>= 1)
            acc[e] += __shfl_xor_sync(0xffffffffu, acc[e], off);
    if (lane == 0) {
        float m = acc[0];
#pragma unroll
        for (int e = 1; e < NEXP; e++) m = fmaxf(m, acc[e]);
        float p[NEXP], s = 0.f;
#pragma unroll
        for (int e = 0; e < NEXP; e++) { p[e] = expf(acc[e] - m); s += p[e]; }
        float inv = 1.f / s;
#pragma unroll
        for (int e = 0; e < NEXP; e++) p[e] *= inv;
        int i0 = 0;
#pragma unroll
        for (int e = 1; e < NEXP; e++) if (p[e] > p[i0]) i0 = e;
        int i1 = (i0 == 0) ? 1 : 0;
#pragma unroll
        for (int e = 0; e < NEXP; e++) if (e != i0 && p[e] > p[i1]) i1 = e;
        int pos = atomicAdd(&g_cnt[i0], 1);
        g_elist[i0 * T_TOK + pos] = t; g_ew[i0 * T_TOK + pos] = p[i0];
        pos = atomicAdd(&g_cnt[i1], 1);
        g_elist[i1 * T_TOK + pos] = t; g_ew[i1 * T_TOK + pos] = p[i1];
    }
}

// ---------------- grouped GEMM: BM=128, BN=128, BK=32, 256 threads (R8-validated) ----------------
// G1:  B = W1[e] fp32 [k=d][n=h]; staged fp32, transpose+cvt -> Bsh [n][k] fp16.
// !G1: B = g_w2h[e] fp16 [k=h][n=d]; staged fp16, transpose (no cvt) -> Bsh.
// Prefetch for chunk i+1 issued after the second barrier of iteration i (race-free).
template <int KDIM, bool G1>
__global__ __launch_bounds__(256) void moe_mma_kernel(const void* __restrict__ Wsrc,
                                                      const float* __restrict__ bias,
                                                      float* __restrict__ out) {
    extern __shared__ __align__(16) char smem[];
    __half* Ash[2] = {(__half*)(smem + OFF_ASH0), (__half*)(smem + OFF_ASH1)};
    __half* Bsh    = (__half*)(smem + OFF_BSH);
    int*    stok   = (int*)(smem + OFF_TOK);
    const uint32_t sb = smem_to_u32(smem);

    const int e = blockIdx.z;
    const int cnt = g_cnt[e];
    const int m0 = blockIdx.y * 128;
    if (m0 >= cnt) return;
    const int base = g_base[e];
    const int n0 = blockIdx.x * 128;
    const int tid = threadIdx.x;
    const int lane = tid & 31, wid = tid >> 5;
    const int wm = wid & 1, wn = wid >> 1;
    constexpr int NDIM = G1 ? HDIM : DDIM;

    if (tid < 128) {
        int r = m0 + tid; if (r >= cnt) r = cnt - 1;
        stok[tid] = G1 ? g_elist[e * T_TOK + r] : (base + r);
    }
    __syncthreads();

    const __half* Abase = G1 ? g_xh : g_h;
    const float*  Bf = (const float*)Wsrc + (G1 ? (size_t)e * DDIM * HDIM : 0);
    const __half* Bh = g_w2h + (size_t)e * HDIM * DDIM;

    auto issue_loads = [&](int it, int b) {
        const int k0 = it * 32;
        const uint32_t abuf = sb + (b ? OFF_ASH1 : OFF_ASH0);
        const uint32_t sbuf = sb + (b ? OFF_STAGE1 : OFF_STAGE0);
        // A: 128 rows x 32 k fp16 = 512 x 16B chunks
#pragma unroll
        for (int j = 0; j < 2; j++) {
            int u = tid + j * 256;
            int m = u >> 2, kq = u & 3;
            CP_ASYNC16(abuf + m * 80 + kq * 16,
                       Abase + (size_t)stok[m] * KDIM + k0 + kq * 8);
        }
        if (G1) {
            // B fp32: 32 k x 128 n = 1024 x 16B chunks, stage stride 132 floats
#pragma unroll
            for (int j = 0; j < 4; j++) {
                int u = tid + j * 256;
                int k = u >> 5, nq = u & 31;
                CP_ASYNC16(sbuf + (k * 132 + nq * 4) * 4,
                           Bf + (size_t)(k0 + k) * NDIM + n0 + nq * 4);
            }
        } else {
            // B fp16: 32 k x 128 n = 512 x 16B chunks, stage stride 136 halves
#pragma unroll
            for (int j = 0; j < 2; j++) {
                int u = tid + j * 256;
                int k = u >> 4, nq = u & 15;
                CP_ASYNC16(sbuf + (k * 136 + nq * 8) * 2,
                           Bh + (size_t)(k0 + k) * NDIM + n0 + nq * 8);
            }
        }
        asm volatile("cp.async.commit_group;" ::: "memory");
    };

    float acc[4][4][4];
#pragma unroll
    for (int i = 0; i < 4; i++)
#pragma unroll
        for (int j = 0; j < 4; j++)
#pragma unroll
            for (int k = 0; k < 4; k++) acc[i][j][k] = 0.f;

    const int qr = lane >> 2;
    const int qc = (lane & 3) * 2;
    const int tn = tid & 127, tkh = tid >> 7;       // tkh 0..1, 16 k each

    constexpr int NIT = KDIM / 32;
    issue_loads(0, 0);

#pragma unroll 1
    for (int i = 0; i < NIT; i++) {
        asm volatile("cp.async.wait_group 0;" ::: "memory");   // group i landed
        __syncthreads();

        // transpose stage[i&1] [k][n] -> Bsh [n][k]
        if (G1) {
            const float* st = (const float*)(smem + (i & 1 ? OFF_STAGE1 : OFF_STAGE0));
            __half2 hbuf[8];
#pragma unroll
            for (int kk = 0; kk < 16; kk += 2)
                hbuf[kk / 2] = __floats2half2_rn(st[(tkh * 16 + kk) * 132 + tn],
                                                 st[(tkh * 16 + kk + 1) * 132 + tn]);
            *(uint4*)(Bsh + tn * 40 + tkh * 16)     = *(const uint4*)(hbuf);
            *(uint4*)(Bsh + tn * 40 + tkh * 16 + 8) = *(const uint4*)(hbuf + 4);
        } else {
            const __half* st = (const __half*)(smem + (i & 1 ? OFF_STAGE1 : OFF_STAGE0));
            __half hbuf[16];
#pragma unroll
            for (int kk = 0; kk < 16; kk++)
                hbuf[kk] = st[(tkh * 16 + kk) * 136 + tn];
            *(uint4*)(Bsh + tn * 40 + tkh * 16)     = *(const uint4*)(hbuf);
            *(uint4*)(Bsh + tn * 40 + tkh * 16 + 8) = *(const uint4*)(hbuf + 8);
        }
        __syncthreads();   // Bsh ready; prior readers of buffers (i+1)&1 are done

        if (i + 1 < NIT) issue_loads(i + 1, (i + 1) & 1);   // overlaps MMA below

        const __half* As = Ash[i & 1];
#pragma unroll
        for (int ks = 0; ks < 2; ks++) {
            const int kk = ks * 16 + qc;
            uint32_t a[4][4];
#pragma unroll
            for (int mt = 0; mt < 4; mt++) {
                const __half* p = As + (wm * 64 + mt * 16 + qr) * 40 + kk;
                a[mt][0] = *(const uint32_t*)(p);
                a[mt][1] = *(const uint32_t*)(p + 320);
                a[mt][2] = *(const uint32_t*)(p + 8);
                a[mt][3] = *(const uint32_t*)(p + 328);
            }
            uint32_t bfr[4][2];
#pragma unroll
            for (int nt = 0; nt < 4; nt++) {
                const __half* p = Bsh + (wn * 32 + nt * 8 + qr) * 40 + kk;
                bfr[nt][0] = *(const uint32_t*)(p);
                bfr[nt][1] = *(const uint32_t*)(p + 8);
            }
#pragma unroll
            for (int mt = 0; mt < 4; mt++)
#pragma unroll
                for (int nt = 0; nt < 4; nt++)
                    MMA16816(acc[mt][nt], a[mt], bfr[nt][0], bfr[nt][1]);
        }
    }

    const int r0 = lane >> 2;
    const int c0l = (lane & 3) * 2;

    if (G1) {
#pragma unroll
        for (int mt = 0; mt < 4; mt++)
#pragma unroll
            for (int hr = 0; hr < 2; hr++) {
                int slot = m0 + wm * 64 + mt * 16 + hr * 8 + r0;
                if (slot < cnt) {
                    __half* hrow = g_h + (size_t)(base + slot) * HDIM;
#pragma unroll
                    for (int nt = 0; nt < 4; nt++) {
                        int n = n0 + wn * 32 + nt * 8 + c0l;
                        float v0 = acc[mt][nt][hr * 2]     + bias[(size_t)e * NDIM + n];
                        float v1 = acc[mt][nt][hr * 2 + 1] + bias[(size_t)e * NDIM + n + 1];
                        *(__half2*)(hrow + n) = __floats2half2_rn(gelu_f(v0), gelu_f(v1));
                    }
                }
            }
    } else {
#pragma unroll
        for (int mt = 0; mt < 4; mt++)
#pragma unroll
            for (int hr = 0; hr < 2; hr++) {
                int slot = m0 + wm * 64 + mt * 16 + hr * 8 + r0;
                if (slot < cnt) {
                    int tok = g_elist[e * T_TOK + slot];
                    float wgt = g_ew[e * T_TOK + slot];
                    float* orow = out + (size_t)tok * DDIM;
#pragma unroll
                    for (int nt = 0; nt < 4; nt++) {
                        int n = n0 + wn * 32 + nt * 8 + c0l;
                        float v0 = (acc[mt][nt][hr * 2]     + bias[(size_t)e * NDIM + n])     * wgt;
                        float v1 = (acc[mt][nt][hr * 2 + 1] + bias[(size_t)e * NDIM + n + 1]) * wgt;
                        atomicAdd(orow + n, v0);
                        atomicAdd(orow + n + 1, v1);
                    }
                }
            }
    }
}

// ---------------- fallback: recompute any all-zero token (insurance) ----------------
__global__ __launch_bounds__(256) void fallback_kernel(
        const float* __restrict__ x,  const float* __restrict__ Wg,
        const float* __restrict__ W1, const float* __restrict__ b1,
        const float* __restrict__ W2, const float* __restrict__ b2,
        float* __restrict__ out) {
    const int t = blockIdx.x;
    float* orow = out + (size_t)t * DDIM;
    const int tid = threadIdx.x;

    __shared__ int nz;
    if (tid == 0) nz = 0;
    __syncthreads();
    for (int d = tid; d < DDIM; d += 256)
        if (fabsf(orow[d]) > 1e-10f) nz = 1;
    __syncthreads();
    if (nz) return;

    __shared__ float sx[DDIM];
    __shared__ float sh[HDIM];
    __shared__ float slog[NEXP];
    __shared__ int   sel[2];
    __shared__ float selw[2];

    for (int d = tid; d < DDIM; d += 256) sx[d] = x[(size_t)t * DDIM + d];
    __syncthreads();

    const int wid = tid >> 5, lane = tid & 31;
    if (wid < NEXP) {
        float a = 0.f;
        for (int d = lane; d < DDIM; d += 32) a += sx[d] * Wg[d * NEXP + wid];
#pragma unroll
        for (int o = 16; o; o >>= 1) a += __shfl_xor_sync(0xffffffffu, a, o);
        if (lane == 0) slog[wid] = a;
    }
    __syncthreads();
    if (tid == 0) {
        float m = slog[0];
        for (int e = 1; e < NEXP; e++) m = fmaxf(m, slog[e]);
        float p[NEXP], s = 0.f;
        for (int e = 0; e < NEXP; e++) { p[e] = expf(slog[e] - m); s += p[e]; }
        for (int e = 0; e < NEXP; e++) p[e] /= s;
        int i0 = 0;
        for (int e = 1; e < NEXP; e++) if (p[e] > p[i0]) i0 = e;
        int i1 = (i0 == 0) ? 1 : 0;
        for (int e = 0; e < NEXP; e++) if (e != i0 && p[e] > p[i1]) i1 = e;
        sel[0] = i0; sel[1] = i1; selw[0] = p[i0]; selw[1] = p[i1];
    }
    __syncthreads();

    float yacc[4] = {0.f, 0.f, 0.f, 0.f};
#pragma unroll 1
    for (int kk = 0; kk < 2; kk++) {
        const int e = sel[kk];
        const float w = selw[kk];
        const float* w1 = W1 + (size_t)e * DDIM * HDIM;
        for (int j = tid; j < HDIM; j += 256) {
            float a = b1[e * HDIM + j];
            for (int d = 0; d < DDIM; d++) a += sx[d] * w1[(size_t)d * HDIM + j];
            sh[j] = gelu_f(a);
        }
        __syncthreads();
        const float* w2 = W2 + (size_t)e * HDIM * DDIM;
#pragma unroll
        for (int jj = 0; jj < 4; jj++) {
            int d = tid + jj * 256;
            float a = b2[e * DDIM + d];
            for (int j = 0; j < HDIM; j++) a += sh[j] * w2[(size_t)j * DDIM + d];
            yacc[jj] += w * a;
        }
        __syncthreads();
    }
#pragma unroll
    for (int jj = 0; jj < 4; jj++) orow[tid + jj * 256] = yacc[jj];
}

// ---------------- host launcher ----------------
extern "C" void kernel_launch(void* const* d_in, const int* in_sizes, int n_in,
                              void* d_out, int out_size) {
    const float* x  = (const float*)d_in[0];
    const float* Wg = (const float*)d_in[1];
    const float* W1 = (const float*)d_in[2];
    const float* b1 = (const float*)d_in[3];
    const float* W2 = (const float*)d_in[4];
    const float* b2 = (const float*)d_in[5];
    float* out = (float*)d_out;

    cudaFuncSetAttribute((const void*)moe_mma_kernel<DDIM, true>,
                         cudaFuncAttributeMaxDynamicSharedMemorySize, SMEM_BYTES);
    cudaFuncSetAttribute((const void*)moe_mma_kernel<HDIM, false>,
                         cudaFuncAttributeMaxDynamicSharedMemorySize, SMEM_BYTES);

    zero_out_kernel<<<(T_TOK * DDIM / 4) / 512, 512>>>((float4*)out);
    convert_x_kernel<<<(T_TOK * DDIM / 4) / 256, 256>>>(x);
    convert_w2_kernel<<<(int)(((size_t)NEXP * HDIM * DDIM / 8) / 256), 256>>>(W2);
    route_kernel<<<T_TOK / 8, 256>>>(x, Wg);
    prefix_kernel<<<1, 32>>>();
    moe_mma_kernel<DDIM, true><<<dim3(HDIM / 128, T_TOK / 128, NEXP), 256, SMEM_BYTES>>>(W1, b1, nullptr);
    moe_mma_kernel<HDIM, false><<<dim3(DDIM / 128, T_TOK / 128, NEXP), 256, SMEM_BYTES>>>(nullptr, b2, out);
    fallback_kernel<<<T_TOK, 256>>>(x, Wg, W1, b1, W2, b2, out);
}

// round 15
// speedup vs baseline: 2.4909x; 1.3872x over previous
#include <cuda_runtime.h>
#include <cuda_fp16.h>
#include <cstdint>
#include <math.h>

// ---------------- problem constants ----------------
#define T_TOK 8192
#define NEXP  8
#define DDIM  1024
#define HDIM  4096
#define NPAIR (2 * T_TOK)

// ---------------- device scratch (static; 208 MB total — stay under ~256 MB) ----------------
__device__ __half g_xh [(size_t)T_TOK * DDIM];          // x in fp16             16 MB
__device__ __half g_h  [(size_t)NPAIR * HDIM];          // compact hidden rows  128 MB
__device__ __half g_wt [(size_t)NEXP * DDIM * HDIM];    // fp16 weights (W1, then W2)  64 MB
__device__ int    g_cnt [NEXP];
__device__ int    g_base[NEXP];
__device__ int    g_elist[NEXP * T_TOK];
__device__ float  g_ew  [NEXP * T_TOK];

// ---------------- helpers ----------------
__device__ __forceinline__ uint32_t smem_to_u32(const void* p) {
    uint32_t a;
    asm("{ .reg .u64 t; cvta.to.shared.u64 t, %1; cvt.u32.u64 %0, t; }" : "=r"(a) : "l"(p));
    return a;
}

#define CP_ASYNC16(dst, src) \
    asm volatile("cp.async.cg.shared.global [%0], [%1], 16;" :: "r"(dst), "l"(src) : "memory")

#define LDSM_X4(r0, r1, r2, r3, addr) \
    asm volatile("ldmatrix.sync.aligned.m8n8.x4.shared.b16 {%0,%1,%2,%3}, [%4];" \
        : "=r"(r0), "=r"(r1), "=r"(r2), "=r"(r3) : "r"(addr))

#define LDSM_X4_T(r0, r1, r2, r3, addr) \
    asm volatile("ldmatrix.sync.aligned.m8n8.x4.trans.shared.b16 {%0,%1,%2,%3}, [%4];" \
        : "=r"(r0), "=r"(r1), "=r"(r2), "=r"(r3) : "r"(addr))

#define MMA16816(c, a, b0v, b1v) \
    asm volatile("mma.sync.aligned.m16n8k16.row.col.f32.f16.f16.f32 " \
        "{%0,%1,%2,%3}, {%4,%5,%6,%7}, {%8,%9}, {%0,%1,%2,%3};" \
        : "+f"((c)[0]), "+f"((c)[1]), "+f"((c)[2]), "+f"((c)[3]) \
        : "r"((a)[0]), "r"((a)[1]), "r"((a)[2]), "r"((a)[3]), "r"(b0v), "r"(b1v))

__device__ __forceinline__ float gelu_f(float v) {
    return 0.5f * v * (1.0f + erff(v * 0.70710678118654752440f));
}

// ---------------- small kernels ----------------
__global__ void zero_out_kernel(float4* __restrict__ out) {
    size_t i = (size_t)blockIdx.x * 512 + threadIdx.x;
    out[i] = make_float4(0.f, 0.f, 0.f, 0.f);
    if (blockIdx.x == 0 && threadIdx.x < NEXP) g_cnt[threadIdx.x] = 0;
}

__global__ void convert_x_kernel(const float* __restrict__ x) {
    size_t i = (size_t)blockIdx.x * 256 + threadIdx.x;     // over float4s
    float4 v = ((const float4*)x)[i];
    ((__half2*)g_xh)[2 * i]     = __floats2half2_rn(v.x, v.y);
    ((__half2*)g_xh)[2 * i + 1] = __floats2half2_rn(v.z, v.w);
}

// streaming fp32 -> fp16, layout preserved (used for W1, then W2, into g_wt)
__global__ void convert_w_kernel(const float* __restrict__ w) {
    size_t i = (size_t)blockIdx.x * 256 + threadIdx.x;     // over 8-float groups
    const float4* s = (const float4*)w + 2 * i;
    float4 a = s[0], b = s[1];
    __half2 h[4];
    h[0] = __floats2half2_rn(a.x, a.y);
    h[1] = __floats2half2_rn(a.z, a.w);
    h[2] = __floats2half2_rn(b.x, b.y);
    h[3] = __floats2half2_rn(b.z, b.w);
    ((uint4*)g_wt)[i] = *(const uint4*)h;
}

__global__ void prefix_kernel() {
    if (threadIdx.x == 0) {
        int s = 0;
#pragma unroll
        for (int e = 0; e < NEXP; e++) { g_base[e] = s; s += g_cnt[e]; }
    }
}

// ---------------- routing ----------------
__global__ __launch_bounds__(256) void route_kernel(const float* __restrict__ x,
                                                    const float* __restrict__ wg) {
    int t = blockIdx.x * 8 + (threadIdx.x >> 5);
    int lane = threadIdx.x & 31;
    const float* xr = x + (size_t)t * DDIM;
    float acc[NEXP];
#pragma unroll
    for (int e = 0; e < NEXP; e++) acc[e] = 0.f;
    for (int d = lane; d < DDIM; d += 32) {
        float xv = xr[d];
        const float* wr = wg + d * NEXP;
#pragma unroll
        for (int e = 0; e < NEXP; e++) acc[e] += xv * wr[e];
    }
#pragma unroll
    for (int e = 0; e < NEXP; e++)
#pragma unroll
        for (int off = 16; off; off >>= 1)
            acc[e] += __shfl_xor_sync(0xffffffffu, acc[e], off);
    if (lane == 0) {
        float m = acc[0];
#pragma unroll
        for (int e = 1; e < NEXP; e++) m = fmaxf(m, acc[e]);
        float p[NEXP], s = 0.f;
#pragma unroll
        for (int e = 0; e < NEXP; e++) { p[e] = expf(acc[e] - m); s += p[e]; }
        float inv = 1.f / s;
#pragma unroll
        for (int e = 0; e < NEXP; e++) p[e] *= inv;
        int i0 = 0;
#pragma unroll
        for (int e = 1; e < NEXP; e++) if (p[e] > p[i0]) i0 = e;
        int i1 = (i0 == 0) ? 1 : 0;
#pragma unroll
        for (int e = 0; e < NEXP; e++) if (e != i0 && p[e] > p[i1]) i1 = e;
        int pos = atomicAdd(&g_cnt[i0], 1);
        g_elist[i0 * T_TOK + pos] = t; g_ew[i0 * T_TOK + pos] = p[i0];
        pos = atomicAdd(&g_cnt[i1], 1);
        g_elist[i1 * T_TOK + pos] = t; g_ew[i1 * T_TOK + pos] = p[i1];
    }
}

// ---------------- grouped GEMM: BM=128, BN=128, BK=32, 256 thr, single-barrier loop ----------------
// A [m][k] fp16 (stride 40 halves), B [k][n] fp16 natural layout (stride 136 halves).
// A fragments: ldmatrix.x4; B fragments: ldmatrix.x4.trans (no transpose pass needed).
// Double-buffered; per iteration: wait_group 0 -> __syncthreads -> issue(i+1) -> mma(i).
// The barrier orders iter-(i-1) fragment reads before the cp.async writes reusing that buffer.
template <int KDIM, bool G1>
__global__ __launch_bounds__(256, 2) void moe_mma_kernel(const float* __restrict__ bias,
                                                         float* __restrict__ out) {
    __shared__ __align__(16) __half AshS[2][128 * 40];   // 2 x 10240 B
    __shared__ __align__(16) __half BshS[2][32 * 136];   // 2 x  8704 B
    __shared__ int stok[128];

    const int e = blockIdx.z;
    const int cnt = g_cnt[e];
    const int m0 = blockIdx.y * 128;
    if (m0 >= cnt) return;
    const int base = g_base[e];
    const int n0 = blockIdx.x * 128;
    const int tid = threadIdx.x;
    const int lane = tid & 31, wid = tid >> 5;
    const int wm = wid & 1, wn = wid >> 1;
    constexpr int NDIM = G1 ? HDIM : DDIM;

    if (tid < 128) {
        int r = m0 + tid; if (r >= cnt) r = cnt - 1;
        stok[tid] = G1 ? g_elist[e * T_TOK + r] : (base + r);
    }
    __syncthreads();

    const __half* Abase = G1 ? g_xh : g_h;
    const __half* Bsrc = g_wt + (size_t)e * DDIM * HDIM;   // [k][n], row length NDIM

    const uint32_t sa0 = smem_to_u32(AshS[0]), sa1 = smem_to_u32(AshS[1]);
    const uint32_t sb0 = smem_to_u32(BshS[0]), sb1 = smem_to_u32(BshS[1]);

    auto issue_loads = [&](int it, int b) {
        const int k0 = it * 32;
        const uint32_t abuf = b ? sa1 : sa0;
        const uint32_t bbuf = b ? sb1 : sb0;
        // A: 128 rows x 32 k fp16 = 512 x 16B chunks
#pragma unroll
        for (int j = 0; j < 2; j++) {
            int u = tid + j * 256;
            int m = u >> 2, kq = u & 3;
            CP_ASYNC16(abuf + m * 80 + kq * 16,
                       Abase + (size_t)stok[m] * KDIM + k0 + kq * 8);
        }
        // B: 32 k-rows x 128 n fp16, natural [k][n], 512 x 16B chunks
#pragma unroll
        for (int j = 0; j < 2; j++) {
            int u = tid + j * 256;
            int k = u >> 4, nq = u & 15;
            CP_ASYNC16(bbuf + k * 272 + nq * 16,
                       Bsrc + (size_t)(k0 + k) * NDIM + n0 + nq * 8);
        }
        asm volatile("cp.async.commit_group;" ::: "memory");
    };

    float acc[4][4][4];
#pragma unroll
    for (int i = 0; i < 4; i++)
#pragma unroll
        for (int j = 0; j < 4; j++)
#pragma unroll
            for (int k = 0; k < 4; k++) acc[i][j][k] = 0.f;

    // ldmatrix per-lane byte offsets
    // A (non-trans, [m][k] stride 40h): lanes 0-7 rows 0-7 (k0-7), 8-15 rows 8-15,
    //   16-23 rows 0-7 (k8-15), 24-31 rows 8-15 (k8-15) -> regs {a0,a1,a2,a3}
    const uint32_t aoff = ((wm * 64 + (lane & 15)) * 40 + (lane >> 4) * 8) * 2;
    // B (trans, [k][n] stride 136h): matrix m=lane>>3: k-octet = m&1, n-octet = m>>1
    //   -> regs {b0(n0),b1(n0),b0(n8),b1(n8)}
    const uint32_t boff = ((((lane >> 3) & 1) * 8 + (lane & 7)) * 136
                          + wn * 32 + (lane >> 4) * 8) * 2;

    constexpr int NIT = KDIM / 32;
    issue_loads(0, 0);

#pragma unroll 1
    for (int i = 0; i < NIT; i++) {
        asm volatile("cp.async.wait_group 0;" ::: "memory");   // own copies of group i done
        __syncthreads();                                       // all threads' copies visible
        if (i + 1 < NIT) issue_loads(i + 1, (i + 1) & 1);      // overlaps MMA below

        const uint32_t aA = (i & 1 ? sa1 : sa0) + aoff;
        const uint32_t bA = (i & 1 ? sb1 : sb0) + boff;
#pragma unroll
        for (int ks = 0; ks < 2; ks++) {
            uint32_t a[4][4];
#pragma unroll
            for (int mt = 0; mt < 4; mt++)
                LDSM_X4(a[mt][0], a[mt][1], a[mt][2], a[mt][3],
                        aA + mt * 1280 + ks * 32);
            uint32_t bfr[4][2];
#pragma unroll
            for (int ntp = 0; ntp < 2; ntp++)
                LDSM_X4_T(bfr[2 * ntp][0], bfr[2 * ntp][1],
                          bfr[2 * ntp + 1][0], bfr[2 * ntp + 1][1],
                          bA + ks * 4352 + ntp * 32);
#pragma unroll
            for (int mt = 0; mt < 4; mt++)
#pragma unroll
                for (int nt = 0; nt < 4; nt++)
                    MMA16816(acc[mt][nt], a[mt], bfr[nt][0], bfr[nt][1]);
        }
    }

    const int r0 = lane >> 2;
    const int c0l = (lane & 3) * 2;

    if (G1) {
#pragma unroll
        for (int mt = 0; mt < 4; mt++)
#pragma unroll
            for (int hr = 0; hr < 2; hr++) {
                int slot = m0 + wm * 64 + mt * 16 + hr * 8 + r0;
                if (slot < cnt) {
                    __half* hrow = g_h + (size_t)(base + slot) * HDIM;
#pragma unroll
                    for (int nt = 0; nt < 4; nt++) {
                        int n = n0 + wn * 32 + nt * 8 + c0l;
                        float v0 = acc[mt][nt][hr * 2]     + bias[(size_t)e * NDIM + n];
                        float v1 = acc[mt][nt][hr * 2 + 1] + bias[(size_t)e * NDIM + n + 1];
                        *(__half2*)(hrow + n) = __floats2half2_rn(gelu_f(v0), gelu_f(v1));
                    }
                }
            }
    } else {
#pragma unroll
        for (int mt = 0; mt < 4; mt++)
#pragma unroll
            for (int hr = 0; hr < 2; hr++) {
                int slot = m0 + wm * 64 + mt * 16 + hr * 8 + r0;
                if (slot < cnt) {
                    int tok = g_elist[e * T_TOK + slot];
                    float wgt = g_ew[e * T_TOK + slot];
                    float* orow = out + (size_t)tok * DDIM;
#pragma unroll
                    for (int nt = 0; nt < 4; nt++) {
                        int n = n0 + wn * 32 + nt * 8 + c0l;
                        float v0 = (acc[mt][nt][hr * 2]     + bias[(size_t)e * NDIM + n])     * wgt;
                        float v1 = (acc[mt][nt][hr * 2 + 1] + bias[(size_t)e * NDIM + n + 1]) * wgt;
                        atomicAdd(orow + n, v0);
                        atomicAdd(orow + n + 1, v1);
                    }
                }
            }
    }
}

// ---------------- fallback: recompute any all-zero token (insurance) ----------------
__global__ __launch_bounds__(256) void fallback_kernel(
        const float* __restrict__ x,  const float* __restrict__ Wg,
        const float* __restrict__ W1, const float* __restrict__ b1,
        const float* __restrict__ W2, const float* __restrict__ b2,
        float* __restrict__ out) {
    const int t = blockIdx.x;
    float* orow = out + (size_t)t * DDIM;
    const int tid = threadIdx.x;

    __shared__ int nz;
    if (tid == 0) nz = 0;
    __syncthreads();
    for (int d = tid; d < DDIM; d += 256)
        if (fabsf(orow[d]) > 1e-10f) nz = 1;
    __syncthreads();
    if (nz) return;

    __shared__ float sx[DDIM];
    __shared__ float sh[HDIM];
    __shared__ float slog[NEXP];
    __shared__ int   sel[2];
    __shared__ float selw[2];

    for (int d = tid; d < DDIM; d += 256) sx[d] = x[(size_t)t * DDIM + d];
    __syncthreads();

    const int wid = tid >> 5, lane = tid & 31;
    if (wid < NEXP) {
        float a = 0.f;
        for (int d = lane; d < DDIM; d += 32) a += sx[d] * Wg[d * NEXP + wid];
#pragma unroll
        for (int o = 16; o; o >>= 1) a += __shfl_xor_sync(0xffffffffu, a, o);
        if (lane == 0) slog[wid] = a;
    }
    __syncthreads();
    if (tid == 0) {
        float m = slog[0];
        for (int e = 1; e < NEXP; e++) m = fmaxf(m, slog[e]);
        float p[NEXP], s = 0.f;
        for (int e = 0; e < NEXP; e++) { p[e] = expf(slog[e] - m); s += p[e]; }
        for (int e = 0; e < NEXP; e++) p[e] /= s;
        int i0 = 0;
        for (int e = 1; e < NEXP; e++) if (p[e] > p[i0]) i0 = e;
        int i1 = (i0 == 0) ? 1 : 0;
        for (int e = 0; e < NEXP; e++) if (e != i0 && p[e] > p[i1]) i1 = e;
        sel[0] = i0; sel[1] = i1; selw[0] = p[i0]; selw[1] = p[i1];
    }
    __syncthreads();

    float yacc[4] = {0.f, 0.f, 0.f, 0.f};
#pragma unroll 1
    for (int kk = 0; kk < 2; kk++) {
        const int e = sel[kk];
        const float w = selw[kk];
        const float* w1 = W1 + (size_t)e * DDIM * HDIM;
        for (int j = tid; j < HDIM; j += 256) {
            float a = b1[e * HDIM + j];
            for (int d = 0; d < DDIM; d++) a += sx[d] * w1[(size_t)d * HDIM + j];
            sh[j] = gelu_f(a);
        }
        __syncthreads();
        const float* w2 = W2 + (size_t)e * HDIM * DDIM;
#pragma unroll
        for (int jj = 0; jj < 4; jj++) {
            int d = tid + jj * 256;
            float a = b2[e * DDIM + d];
            for (int j = 0; j < HDIM; j++) a += sh[j] * w2[(size_t)j * DDIM + d];
            yacc[jj] += w * a;
        }
        __syncthreads();
    }
#pragma unroll
    for (int jj = 0; jj < 4; jj++) orow[tid + jj * 256] = yacc[jj];
}

// ---------------- host launcher ----------------
extern "C" void kernel_launch(void* const* d_in, const int* in_sizes, int n_in,
                              void* d_out, int out_size) {
    const float* x  = (const float*)d_in[0];
    const float* Wg = (const float*)d_in[1];
    const float* W1 = (const float*)d_in[2];
    const float* b1 = (const float*)d_in[3];
    const float* W2 = (const float*)d_in[4];
    const float* b2 = (const float*)d_in[5];
    float* out = (float*)d_out;

    const int wgrid = (int)(((size_t)NEXP * DDIM * HDIM / 8) / 256);

    zero_out_kernel<<<(T_TOK * DDIM / 4) / 512, 512>>>((float4*)out);
    convert_x_kernel<<<(T_TOK * DDIM / 4) / 256, 256>>>(x);
    route_kernel<<<T_TOK / 8, 256>>>(x, Wg);
    prefix_kernel<<<1, 32>>>();
    convert_w_kernel<<<wgrid, 256>>>(W1);
    moe_mma_kernel<DDIM, true><<<dim3(HDIM / 128, T_TOK / 128, NEXP), 256>>>(b1, nullptr);
    convert_w_kernel<<<wgrid, 256>>>(W2);
    moe_mma_kernel<HDIM, false><<<dim3(DDIM / 128, T_TOK / 128, NEXP), 256>>>(b2, out);
    fallback_kernel<<<T_TOK, 256>>>(x, Wg, W1, b1, W2, b2, out);
}